// round 5
// baseline (speedup 1.0000x reference)
#include <cuda_runtime.h>
#include <math.h>
#include <stdint.h>

#define OUT_DIM 2048
#define IN_DIM  2048
#define RANK    4
#define NORM_EPS 1e-6f
#define MAG_EPS  1e-6f

// GEMM tiling
#define BM 128
#define BN 256
#define BK 32
#define KT (IN_DIM / BK)          // 64 k-tiles
#define PAD 36                    // floats per smem row (144B): conflict-free LDSM
#define STAGES 3
#define A_SM_BYTES (BM * PAD * 4)            // 18432
#define STAGE_BYTES ((BM + BN) * PAD * 4)    // 55296
#define SMEM_TOTAL (STAGES * STAGE_BYTES)    // 165888

// scratch: effective weight (tf32-rounded fp32 bit patterns), row-major [out][in]
__device__ float g_W[OUT_DIM * IN_DIM];
// stats: [0..3]=normA, [4..7]=normB, [8..11]=g
__device__ float g_stats[3 * RANK];

// ---------------------------------------------------------------------------
// PTX helpers (sm_80+ portable)
// ---------------------------------------------------------------------------
__device__ __forceinline__ uint32_t smem_u32(const void* p) {
    uint32_t a;
    asm("{ .reg .u64 t; cvta.to.shared.u64 t, %1; cvt.u32.u64 %0, t; }" : "=r"(a) : "l"(p));
    return a;
}
#define CP_ASYNC16(dst, src) \
    asm volatile("cp.async.cg.shared.global [%0], [%1], 16;" :: "r"(dst), "l"(src))
#define CP_COMMIT() asm volatile("cp.async.commit_group;" ::: "memory")
#define CP_WAIT(n)  asm volatile("cp.async.wait_group %0;" :: "n"(n) : "memory")
#define LDSM4(r0, r1, r2, r3, addr) \
    asm volatile("ldmatrix.sync.aligned.m8n8.x4.shared.b16 {%0,%1,%2,%3}, [%4];" \
        : "=r"(r0), "=r"(r1), "=r"(r2), "=r"(r3) : "r"(addr))

__device__ __forceinline__ void mma_tf32(float* d, const uint32_t* a, uint32_t b0, uint32_t b1) {
    asm volatile("mma.sync.aligned.m16n8k8.row.col.f32.tf32.tf32.f32 "
        "{%0,%1,%2,%3}, {%4,%5,%6,%7}, {%8,%9}, {%0,%1,%2,%3};"
        : "+f"(d[0]), "+f"(d[1]), "+f"(d[2]), "+f"(d[3])
        : "r"(a[0]), "r"(a[1]), "r"(a[2]), "r"(a[3]), "r"(b0), "r"(b1));
}

// ---------------------------------------------------------------------------
// Kernel 1: per-rank norms + softplus magnitude
// ---------------------------------------------------------------------------
__global__ void stats_kernel(const float* __restrict__ A,
                             const float* __restrict__ Bm,
                             const float* __restrict__ mag) {
    int r = threadIdx.x >> 5, lane = threadIdx.x & 31;
    float sa = 0.f, sb = 0.f;
    for (int o = lane; o < OUT_DIM; o += 32) { float v = A[o * RANK + r]; sa += v * v; }
    for (int i = lane; i < IN_DIM; i += 32)  { float v = Bm[r * IN_DIM + i]; sb += v * v; }
#pragma unroll
    for (int off = 16; off; off >>= 1) {
        sa += __shfl_xor_sync(0xffffffffu, sa, off);
        sb += __shfl_xor_sync(0xffffffffu, sb, off);
    }
    if (lane == 0) {
        g_stats[r]        = fmaxf(sqrtf(sa), NORM_EPS);
        g_stats[RANK + r] = fmaxf(sqrtf(sb), NORM_EPS);
        float m = mag[r];
        float sp = (m > 15.f) ? m : log1pf(expf(m));
        g_stats[2 * RANK + r] = sp + MAG_EPS;
    }
}

// ---------------------------------------------------------------------------
// Kernel 2: materialize W[o][i] = lut[idx]*sum_r coef[o][r]*|B[r][i]|, tf32-RNA
// ---------------------------------------------------------------------------
__global__ void build_w_kernel(const float* __restrict__ A,
                               const float* __restrict__ Bm,
                               const int*   __restrict__ idx,
                               const float* __restrict__ lut) {
    int t = blockIdx.x * blockDim.x + threadIdx.x;
    int per_row = IN_DIM / 4;
    int o  = t / per_row;
    int i4 = (t - o * per_row) * 4;

    float coef[RANK];
#pragma unroll
    for (int r = 0; r < RANK; r++)
        coef[r] = fabsf(A[o * RANK + r]) * g_stats[2 * RANK + r]
                  / (g_stats[r] * g_stats[RANK + r]);

    float s[4] = {0.f, 0.f, 0.f, 0.f};
#pragma unroll
    for (int r = 0; r < RANK; r++) {
        float4 bv = *(const float4*)(Bm + r * IN_DIM + i4);
        s[0] += coef[r] * fabsf(bv.x);
        s[1] += coef[r] * fabsf(bv.y);
        s[2] += coef[r] * fabsf(bv.z);
        s[3] += coef[r] * fabsf(bv.w);
    }
    int4 iv = *(const int4*)(idx + o * IN_DIM + i4);
    float w0 = lut[iv.x] * s[0], w1 = lut[iv.y] * s[1];
    float w2 = lut[iv.z] * s[2], w3 = lut[iv.w] * s[3];
    uint32_t u0, u1, u2, u3;
    asm("cvt.rna.tf32.f32 %0, %1;" : "=r"(u0) : "f"(w0));
    asm("cvt.rna.tf32.f32 %0, %1;" : "=r"(u1) : "f"(w1));
    asm("cvt.rna.tf32.f32 %0, %1;" : "=r"(u2) : "f"(w2));
    asm("cvt.rna.tf32.f32 %0, %1;" : "=r"(u3) : "f"(w3));
    float4 w;
    w.x = __uint_as_float(u0); w.y = __uint_as_float(u1);
    w.z = __uint_as_float(u2); w.w = __uint_as_float(u3);
    *(float4*)(g_W + o * IN_DIM + i4) = w;
}

// ---------------------------------------------------------------------------
// Kernel 3: tf32 mma.sync GEMM. 128x256 CTA tile, 512 threads (16 warps,
// 64x32 warp tiles -> 4 warps/SMSP), 3-stage cp.async pipeline.
// Y[m][n] = sum_k X[m][k]*W[n][k] + bias[n]
// ---------------------------------------------------------------------------
__global__ __launch_bounds__(512, 1)
void gemm_mma(const float* __restrict__ X,
              const float* __restrict__ bias,
              float* __restrict__ Y) {
    extern __shared__ char smem[];
    const uint32_t sb = smem_u32(smem);
    const int tid = threadIdx.x, lane = tid & 31, wid = tid >> 5;
    const int wm = wid & 1, wn = wid >> 1;       // 2x8 warp grid, 64x32 warp tile
    const int bm = blockIdx.y * BM, bn = blockIdx.x * BN;

    // ldmatrix per-thread base offsets (x4: lane -> matrix lane>>3, row lane&7)
    const int mat = lane >> 3, rowin = lane & 7;
    // A x4 order: {(m0..7,k0..3),(m8..15,k0..3),(m0..7,k4..7),(m8..15,k4..7)}
    const uint32_t a_base = ((uint32_t)(wm * 64 + (mat & 1) * 8 + rowin) * PAD + (mat >> 1) * 4) * 4;
    // B x4 order: {(n0..7,k0..3),(n0..7,k4..7),(n8..15,k0..3),(n8..15,k4..7)}
    const uint32_t b_base = ((uint32_t)(wn * 32 + (mat >> 1) * 8 + rowin) * PAD + (mat & 1) * 4) * 4;

    const float* Xb = X   + (size_t)bm * IN_DIM;
    const float* Wb = g_W + (size_t)bn * IN_DIM;

    float acc[4][4][4];
#pragma unroll
    for (int i = 0; i < 4; i++)
#pragma unroll
        for (int j = 0; j < 4; j++)
#pragma unroll
            for (int k = 0; k < 4; k++) acc[i][j][k] = 0.f;

    // ---- async stage loader: 16B chunks; A=1024 chunks (2/thr), B=2048 (4/thr)
    auto load_stage = [&](int s, int kt) {
        const uint32_t abase = sb + s * STAGE_BYTES;
        const uint32_t bbase = abase + A_SM_BYTES;
        const int kc = kt * BK;
#pragma unroll
        for (int i = 0; i < 2; i++) {
            int id = tid + i * 512;
            int r = id >> 3, c = (id & 7) * 4;
            CP_ASYNC16(abase + ((uint32_t)r * PAD + c) * 4,
                       Xb + (size_t)r * IN_DIM + kc + c);
        }
#pragma unroll
        for (int i = 0; i < 4; i++) {
            int id = tid + i * 512;
            int r = id >> 3, c = (id & 7) * 4;
            CP_ASYNC16(bbase + ((uint32_t)r * PAD + c) * 4,
                       Wb + (size_t)r * IN_DIM + kc + c);
        }
    };

    auto compute_stage = [&](int s) {
        const uint32_t abase = sb + s * STAGE_BYTES + a_base;
        const uint32_t bbase = sb + s * STAGE_BYTES + A_SM_BYTES + b_base;
#pragma unroll
        for (int ks = 0; ks < BK / 8; ks++) {
            uint32_t af[4][4], bf[2][4];
#pragma unroll
            for (int mt = 0; mt < 4; mt++)
                LDSM4(af[mt][0], af[mt][1], af[mt][2], af[mt][3],
                      abase + (uint32_t)mt * 16 * PAD * 4 + ks * 32);
#pragma unroll
            for (int ng = 0; ng < 2; ng++)
                LDSM4(bf[ng][0], bf[ng][1], bf[ng][2], bf[ng][3],
                      bbase + (uint32_t)ng * 16 * PAD * 4 + ks * 32);
#pragma unroll
            for (int mt = 0; mt < 4; mt++)
#pragma unroll
                for (int j = 0; j < 4; j++)
                    mma_tf32(acc[mt][j], af[mt],
                             bf[j >> 1][(j & 1) * 2], bf[j >> 1][(j & 1) * 2 + 1]);
        }
    };

    // ---- pipeline ----
#pragma unroll
    for (int s = 0; s < STAGES - 1; s++) { load_stage(s, s); CP_COMMIT(); }

    for (int kt = 0; kt < KT; kt++) {
        CP_WAIT(1);
        __syncthreads();
        if (kt + STAGES - 1 < KT) load_stage((kt + STAGES - 1) % STAGES, kt + STAGES - 1);
        CP_COMMIT();
        compute_stage(kt % STAGES);
    }

    // ---- epilogue ----
    const int group = lane >> 2, tidg = lane & 3;
#pragma unroll
    for (int j = 0; j < 4; j++) {
        int col = bn + wn * 32 + j * 8 + tidg * 2;
        float b0 = bias[col], b1 = bias[col + 1];
#pragma unroll
        for (int mt = 0; mt < 4; mt++) {
            int r0 = bm + wm * 64 + mt * 16 + group;
            float2 v0, v1;
            v0.x = acc[mt][j][0] + b0; v0.y = acc[mt][j][1] + b1;
            v1.x = acc[mt][j][2] + b0; v1.y = acc[mt][j][3] + b1;
            *(float2*)(Y + (size_t)r0 * OUT_DIM + col)       = v0;
            *(float2*)(Y + (size_t)(r0 + 8) * OUT_DIM + col) = v1;
        }
    }
}

// ---------------------------------------------------------------------------
extern "C" void kernel_launch(void* const* d_in, const int* in_sizes, int n_in,
                              void* d_out, int out_size) {
    const float* x       = (const float*)d_in[0];
    const int*   indices = (const int*)  d_in[1];
    const float* lut     = (const float*)d_in[2];
    const float* A       = (const float*)d_in[3];
    const float* Bm      = (const float*)d_in[4];
    const float* mag     = (const float*)d_in[5];
    const float* bias    = (const float*)d_in[6];
    float* y = (float*)d_out;
    const int M = out_size / OUT_DIM;   // 8192

    stats_kernel<<<1, 128>>>(A, Bm, mag);
    build_w_kernel<<<(OUT_DIM * IN_DIM / 4) / 256, 256>>>(A, Bm, indices, lut);

    static int configured = 0;
    if (!configured) {
        cudaFuncSetAttribute(gemm_mma, cudaFuncAttributeMaxDynamicSharedMemorySize, SMEM_TOTAL);
        configured = 1;
    }
    gemm_mma<<<dim3(OUT_DIM / BN, M / BM), 512, SMEM_TOTAL>>>(x, bias, y);
}

// round 7
// speedup vs baseline: 1.5440x; 1.5440x over previous
#include <cuda_runtime.h>
#include <math.h>
#include <stdint.h>

#define OUT_DIM 2048
#define IN_DIM  2048
#define RANK    4
#define NORM_EPS 1e-6f
#define MAG_EPS  1e-6f

// GEMM tiling (R3 config: 8 warps, 64x64 warp tiles)
#define BM 128
#define BN 256
#define BK 32
#define KT (IN_DIM / BK)          // 64 k-tiles
#define PAD 36                    // floats per smem row (144B): conflict-free LDSM
#define STAGES 4
#define A_SM_BYTES (BM * PAD * 4)            // 18432
#define STAGE_BYTES ((BM + BN) * PAD * 4)    // 55296
#define SMEM_TOTAL (STAGES * STAGE_BYTES)    // 221184

// scratch: effective weight (tf32-rounded fp32 bit patterns), row-major [out][in]
__device__ float g_W[OUT_DIM * IN_DIM];
// stats: [0..3]=normA, [4..7]=normB, [8..11]=g
__device__ float g_stats[3 * RANK];

// ---------------------------------------------------------------------------
// PTX helpers (sm_80+ portable)
// ---------------------------------------------------------------------------
__device__ __forceinline__ uint32_t smem_u32(const void* p) {
    uint32_t a;
    asm("{ .reg .u64 t; cvta.to.shared.u64 t, %1; cvt.u32.u64 %0, t; }" : "=r"(a) : "l"(p));
    return a;
}
#define CP_ASYNC16(dst, src) \
    asm volatile("cp.async.cg.shared.global [%0], [%1], 16;" :: "r"(dst), "l"(src))
#define CP_COMMIT() asm volatile("cp.async.commit_group;" ::: "memory")
#define CP_WAIT(n)  asm volatile("cp.async.wait_group %0;" :: "n"(n) : "memory")
#define LDSM4(r0, r1, r2, r3, addr) \
    asm volatile("ldmatrix.sync.aligned.m8n8.x4.shared.b16 {%0,%1,%2,%3}, [%4];" \
        : "=r"(r0), "=r"(r1), "=r"(r2), "=r"(r3) : "r"(addr))

__device__ __forceinline__ void mma_tf32(float* d, const uint32_t* a, uint32_t b0, uint32_t b1) {
    asm volatile("mma.sync.aligned.m16n8k8.row.col.f32.tf32.tf32.f32 "
        "{%0,%1,%2,%3}, {%4,%5,%6,%7}, {%8,%9}, {%0,%1,%2,%3};"
        : "+f"(d[0]), "+f"(d[1]), "+f"(d[2]), "+f"(d[3])
        : "r"(a[0]), "r"(a[1]), "r"(a[2]), "r"(a[3]), "r"(b0), "r"(b1));
}

// ---------------------------------------------------------------------------
// Kernel 1: per-rank norms + softplus magnitude
// ---------------------------------------------------------------------------
__global__ void stats_kernel(const float* __restrict__ A,
                             const float* __restrict__ Bm,
                             const float* __restrict__ mag) {
    int r = threadIdx.x >> 5, lane = threadIdx.x & 31;
    float sa = 0.f, sb = 0.f;
    for (int o = lane; o < OUT_DIM; o += 32) { float v = A[o * RANK + r]; sa += v * v; }
    for (int i = lane; i < IN_DIM; i += 32)  { float v = Bm[r * IN_DIM + i]; sb += v * v; }
#pragma unroll
    for (int off = 16; off; off >>= 1) {
        sa += __shfl_xor_sync(0xffffffffu, sa, off);
        sb += __shfl_xor_sync(0xffffffffu, sb, off);
    }
    if (lane == 0) {
        g_stats[r]        = fmaxf(sqrtf(sa), NORM_EPS);
        g_stats[RANK + r] = fmaxf(sqrtf(sb), NORM_EPS);
        float m = mag[r];
        float sp = (m > 15.f) ? m : log1pf(expf(m));
        g_stats[2 * RANK + r] = sp + MAG_EPS;
    }
}

// ---------------------------------------------------------------------------
// Kernel 2: materialize W[o][i] = lut[idx]*sum_r coef[o][r]*|B[r][i]|, tf32-RNA
// ---------------------------------------------------------------------------
__global__ void build_w_kernel(const float* __restrict__ A,
                               const float* __restrict__ Bm,
                               const int*   __restrict__ idx,
                               const float* __restrict__ lut) {
    int t = blockIdx.x * blockDim.x + threadIdx.x;
    int per_row = IN_DIM / 4;
    int o  = t / per_row;
    int i4 = (t - o * per_row) * 4;

    float coef[RANK];
#pragma unroll
    for (int r = 0; r < RANK; r++)
        coef[r] = fabsf(A[o * RANK + r]) * g_stats[2 * RANK + r]
                  / (g_stats[r] * g_stats[RANK + r]);

    float s[4] = {0.f, 0.f, 0.f, 0.f};
#pragma unroll
    for (int r = 0; r < RANK; r++) {
        float4 bv = *(const float4*)(Bm + r * IN_DIM + i4);
        s[0] += coef[r] * fabsf(bv.x);
        s[1] += coef[r] * fabsf(bv.y);
        s[2] += coef[r] * fabsf(bv.z);
        s[3] += coef[r] * fabsf(bv.w);
    }
    int4 iv = *(const int4*)(idx + o * IN_DIM + i4);
    float w0 = lut[iv.x] * s[0], w1 = lut[iv.y] * s[1];
    float w2 = lut[iv.z] * s[2], w3 = lut[iv.w] * s[3];
    uint32_t u0, u1, u2, u3;
    asm("cvt.rna.tf32.f32 %0, %1;" : "=r"(u0) : "f"(w0));
    asm("cvt.rna.tf32.f32 %0, %1;" : "=r"(u1) : "f"(w1));
    asm("cvt.rna.tf32.f32 %0, %1;" : "=r"(u2) : "f"(w2));
    asm("cvt.rna.tf32.f32 %0, %1;" : "=r"(u3) : "f"(w3));
    float4 w;
    w.x = __uint_as_float(u0); w.y = __uint_as_float(u1);
    w.z = __uint_as_float(u2); w.w = __uint_as_float(u3);
    *(float4*)(g_W + o * IN_DIM + i4) = w;
}

// ---------------------------------------------------------------------------
// Kernel 3: tf32 mma.sync GEMM. 128x256 CTA tile, 256 threads (8 warps,
// 64x64 warp tiles), 4-stage cp.async pipeline, ks-pipelined fragments.
// Y[m][n] = sum_k X[m][k]*W[n][k] + bias[n]
// ---------------------------------------------------------------------------
__global__ __launch_bounds__(256, 1)
void gemm_mma(const float* __restrict__ X,
              const float* __restrict__ bias,
              float* __restrict__ Y) {
    extern __shared__ char smem[];
    const uint32_t sb = smem_u32(smem);
    const int tid = threadIdx.x, lane = tid & 31, wid = tid >> 5;
    const int wm = wid & 1, wn = wid >> 1;       // 2x4 warp grid, 64x64 warp tile
    const int bm = blockIdx.y * BM, bn = blockIdx.x * BN;

    // ldmatrix per-thread base offsets (x4: lane -> matrix lane>>3, row lane&7)
    const int mat = lane >> 3, rowin = lane & 7;
    // A x4 order: {(m0..7,k0..3),(m8..15,k0..3),(m0..7,k4..7),(m8..15,k4..7)}
    const uint32_t a_base = ((uint32_t)(wm * 64 + (mat & 1) * 8 + rowin) * PAD + (mat >> 1) * 4) * 4;
    // B x4 order: {(n0..7,k0..3),(n0..7,k4..7),(n8..15,k0..3),(n8..15,k4..7)}
    const uint32_t b_base = ((uint32_t)(wn * 64 + (mat >> 1) * 8 + rowin) * PAD + (mat & 1) * 4) * 4;

    const float* Xb = X   + (size_t)bm * IN_DIM;
    const float* Wb = g_W + (size_t)bn * IN_DIM;

    float acc[4][8][4];
#pragma unroll
    for (int i = 0; i < 4; i++)
#pragma unroll
        for (int j = 0; j < 8; j++)
#pragma unroll
            for (int k = 0; k < 4; k++) acc[i][j][k] = 0.f;

    // ---- async stage loader: 16B chunks, A=1024 chunks, B=2048 chunks ----
    auto load_stage = [&](int s, int kt) {
        const uint32_t abase = sb + s * STAGE_BYTES;
        const uint32_t bbase = abase + A_SM_BYTES;
        const int kc = kt * BK;
#pragma unroll
        for (int i = 0; i < 4; i++) {
            int id = tid + i * 256;
            int r = id >> 3, c = (id & 7) * 4;
            CP_ASYNC16(abase + ((uint32_t)r * PAD + c) * 4,
                       Xb + (size_t)r * IN_DIM + kc + c);
        }
#pragma unroll
        for (int i = 0; i < 8; i++) {
            int id = tid + i * 256;
            int r = id >> 3, c = (id & 7) * 4;
            CP_ASYNC16(bbase + ((uint32_t)r * PAD + c) * 4,
                       Wb + (size_t)r * IN_DIM + kc + c);
        }
    };

    // fragment loaders for one ks slice (ks in 0..3, each = 8 k-columns)
    auto ldsm_a = [&](uint32_t s_abase, int ks, uint32_t af[4][4]) {
#pragma unroll
        for (int mt = 0; mt < 4; mt++)
            LDSM4(af[mt][0], af[mt][1], af[mt][2], af[mt][3],
                  s_abase + (uint32_t)mt * 16 * PAD * 4 + ks * 32);
    };
    auto ldsm_b = [&](uint32_t s_bbase, int ks, uint32_t bf[4][4]) {
#pragma unroll
        for (int j = 0; j < 4; j++)
            LDSM4(bf[j][0], bf[j][1], bf[j][2], bf[j][3],
                  s_bbase + (uint32_t)j * 16 * PAD * 4 + ks * 32);
    };

    // ---- pipeline ----
#pragma unroll
    for (int s = 0; s < STAGES - 1; s++) { load_stage(s, s); CP_COMMIT(); }

    uint32_t af[2][4][4], bf[2][4][4];

    for (int kt = 0; kt < KT; kt++) {
        CP_WAIT(2);
        __syncthreads();
        if (kt + STAGES - 1 < KT) load_stage((kt + STAGES - 1) & 3, kt + STAGES - 1);
        CP_COMMIT();

        const int s = kt & 3;
        const uint32_t s_abase = sb + s * STAGE_BYTES + a_base;
        const uint32_t s_bbase = sb + s * STAGE_BYTES + A_SM_BYTES + b_base;

        // prologue fragments for ks=0
        ldsm_a(s_abase, 0, af[0]);
        ldsm_b(s_bbase, 0, bf[0]);

#pragma unroll
        for (int ks = 0; ks < BK / 8; ks++) {
            const int cur = ks & 1, nxt = cur ^ 1;
            if (ks < BK / 8 - 1) {           // prefetch next slice's fragments
                ldsm_a(s_abase, ks + 1, af[nxt]);
                ldsm_b(s_bbase, ks + 1, bf[nxt]);
            }
#pragma unroll
            for (int mt = 0; mt < 4; mt++)
#pragma unroll
                for (int nt = 0; nt < 8; nt++)
                    mma_tf32(acc[mt][nt], af[cur][mt],
                             bf[cur][nt >> 1][(nt & 1) * 2],
                             bf[cur][nt >> 1][(nt & 1) * 2 + 1]);
        }
    }

    // ---- epilogue: c0/c1 at (row=group, col), c2/c3 at row+8 ----
    const int group = lane >> 2, tidg = lane & 3;
#pragma unroll
    for (int nt = 0; nt < 8; nt++) {
        int col = bn + wn * 64 + nt * 8 + tidg * 2;
        float b0 = bias[col], b1 = bias[col + 1];
#pragma unroll
        for (int mt = 0; mt < 4; mt++) {
            int r0 = bm + wm * 64 + mt * 16 + group;
            float2 v0, v1;
            v0.x = acc[mt][nt][0] + b0; v0.y = acc[mt][nt][1] + b1;
            v1.x = acc[mt][nt][2] + b0; v1.y = acc[mt][nt][3] + b1;
            *(float2*)(Y + (size_t)r0 * OUT_DIM + col)       = v0;
            *(float2*)(Y + (size_t)(r0 + 8) * OUT_DIM + col) = v1;
        }
    }
}

// ---------------------------------------------------------------------------
extern "C" void kernel_launch(void* const* d_in, const int* in_sizes, int n_in,
                              void* d_out, int out_size) {
    const float* x       = (const float*)d_in[0];
    const int*   indices = (const int*)  d_in[1];
    const float* lut     = (const float*)d_in[2];
    const float* A       = (const float*)d_in[3];
    const float* Bm      = (const float*)d_in[4];
    const float* mag     = (const float*)d_in[5];
    const float* bias    = (const float*)d_in[6];
    float* y = (float*)d_out;
    const int M = out_size / OUT_DIM;   // 8192

    stats_kernel<<<1, 128>>>(A, Bm, mag);
    build_w_kernel<<<(OUT_DIM * IN_DIM / 4) / 256, 256>>>(A, Bm, indices, lut);

    static int configured = 0;
    if (!configured) {
        cudaFuncSetAttribute(gemm_mma, cudaFuncAttributeMaxDynamicSharedMemorySize, SMEM_TOTAL);
        configured = 1;
    }
    gemm_mma<<<dim3(OUT_DIM / BN, M / BM), 256, SMEM_TOTAL>>>(x, bias, y);
}

// round 8
// speedup vs baseline: 2.3548x; 1.5251x over previous
#include <cuda_runtime.h>
#include <cuda_fp16.h>
#include <math.h>
#include <stdint.h>

#define OUT_DIM 2048
#define IN_DIM  2048
#define MAXM    8192
#define RANK    4
#define NORM_EPS 1e-6f
#define MAG_EPS  1e-6f

// GEMM tiling: 128x256 CTA tile, 8 warps (64x64 warp tiles), fp16 operands
#define BM 128
#define BN 256
#define BK 32
#define KT (IN_DIM / BK)          // 64 k-tiles
#define PADH 40                   // halves per smem row (80B): conflict-free ldmatrix
#define ROWB 80                   // bytes per smem row
#define STAGES 5
#define A_SM_BYTES (BM * ROWB)               // 10240
#define STAGE_BYTES ((BM + BN) * ROWB)       // 30720
#define SMEM_TOTAL (STAGES * STAGE_BYTES)    // 153600

// scratch
__device__ __half g_Wh[OUT_DIM * IN_DIM];    // fp16 effective weight [out][in]
__device__ __half g_Xh[MAXM * IN_DIM];       // fp16 copy of X
__device__ float  g_stats[3 * RANK];         // [0..3]=normA, [4..7]=normB, [8..11]=g

// ---------------------------------------------------------------------------
// PTX helpers (sm_80+ portable)
// ---------------------------------------------------------------------------
__device__ __forceinline__ uint32_t smem_u32(const void* p) {
    uint32_t a;
    asm("{ .reg .u64 t; cvta.to.shared.u64 t, %1; cvt.u32.u64 %0, t; }" : "=r"(a) : "l"(p));
    return a;
}
#define CP_ASYNC16(dst, src) \
    asm volatile("cp.async.cg.shared.global [%0], [%1], 16;" :: "r"(dst), "l"(src))
#define CP_COMMIT() asm volatile("cp.async.commit_group;" ::: "memory")
#define CP_WAIT(n)  asm volatile("cp.async.wait_group %0;" :: "n"(n) : "memory")
#define LDSM4(r0, r1, r2, r3, addr) \
    asm volatile("ldmatrix.sync.aligned.m8n8.x4.shared.b16 {%0,%1,%2,%3}, [%4];" \
        : "=r"(r0), "=r"(r1), "=r"(r2), "=r"(r3) : "r"(addr))

__device__ __forceinline__ void mma_f16(float* d, const uint32_t* a, uint32_t b0, uint32_t b1) {
    asm volatile("mma.sync.aligned.m16n8k16.row.col.f32.f16.f16.f32 "
        "{%0,%1,%2,%3}, {%4,%5,%6,%7}, {%8,%9}, {%0,%1,%2,%3};"
        : "+f"(d[0]), "+f"(d[1]), "+f"(d[2]), "+f"(d[3])
        : "r"(a[0]), "r"(a[1]), "r"(a[2]), "r"(a[3]), "r"(b0), "r"(b1));
}

// ---------------------------------------------------------------------------
// Kernel 1: per-rank norms + softplus magnitude
// ---------------------------------------------------------------------------
__global__ void stats_kernel(const float* __restrict__ A,
                             const float* __restrict__ Bm,
                             const float* __restrict__ mag) {
    int r = threadIdx.x >> 5, lane = threadIdx.x & 31;
    float sa = 0.f, sb = 0.f;
    for (int o = lane; o < OUT_DIM; o += 32) { float v = A[o * RANK + r]; sa += v * v; }
    for (int i = lane; i < IN_DIM; i += 32)  { float v = Bm[r * IN_DIM + i]; sb += v * v; }
#pragma unroll
    for (int off = 16; off; off >>= 1) {
        sa += __shfl_xor_sync(0xffffffffu, sa, off);
        sb += __shfl_xor_sync(0xffffffffu, sb, off);
    }
    if (lane == 0) {
        g_stats[r]        = fmaxf(sqrtf(sa), NORM_EPS);
        g_stats[RANK + r] = fmaxf(sqrtf(sb), NORM_EPS);
        float m = mag[r];
        float sp = (m > 15.f) ? m : log1pf(expf(m));
        g_stats[2 * RANK + r] = sp + MAG_EPS;
    }
}

// ---------------------------------------------------------------------------
// Kernel 2: materialize W[o][i] = lut[idx]*sum_r coef[o][r]*|B[r][i]| as fp16
// ---------------------------------------------------------------------------
__global__ void build_w_kernel(const float* __restrict__ A,
                               const float* __restrict__ Bm,
                               const int*   __restrict__ idx,
                               const float* __restrict__ lut) {
    int t = blockIdx.x * blockDim.x + threadIdx.x;
    int per_row = IN_DIM / 4;
    int o  = t / per_row;
    int i4 = (t - o * per_row) * 4;

    float coef[RANK];
#pragma unroll
    for (int r = 0; r < RANK; r++)
        coef[r] = fabsf(A[o * RANK + r]) * g_stats[2 * RANK + r]
                  / (g_stats[r] * g_stats[RANK + r]);

    float s[4] = {0.f, 0.f, 0.f, 0.f};
#pragma unroll
    for (int r = 0; r < RANK; r++) {
        float4 bv = *(const float4*)(Bm + r * IN_DIM + i4);
        s[0] += coef[r] * fabsf(bv.x);
        s[1] += coef[r] * fabsf(bv.y);
        s[2] += coef[r] * fabsf(bv.z);
        s[3] += coef[r] * fabsf(bv.w);
    }
    int4 iv = *(const int4*)(idx + o * IN_DIM + i4);
    __half2 h0 = __floats2half2_rn(lut[iv.x] * s[0], lut[iv.y] * s[1]);
    __half2 h1 = __floats2half2_rn(lut[iv.z] * s[2], lut[iv.w] * s[3]);
    uint2 pack;
    pack.x = *(uint32_t*)&h0;
    pack.y = *(uint32_t*)&h1;
    *(uint2*)((__half*)g_Wh + (size_t)o * IN_DIM + i4) = pack;
}

// ---------------------------------------------------------------------------
// Kernel 2b: X fp32 -> fp16 (8 elems/thread)
// ---------------------------------------------------------------------------
__global__ void convert_x_kernel(const float* __restrict__ X, int total8) {
    int t = blockIdx.x * blockDim.x + threadIdx.x;
    if (t >= total8) return;
    size_t base = (size_t)t * 8;
    float4 v0 = *(const float4*)(X + base);
    float4 v1 = *(const float4*)(X + base + 4);
    __half2 h0 = __floats2half2_rn(v0.x, v0.y);
    __half2 h1 = __floats2half2_rn(v0.z, v0.w);
    __half2 h2 = __floats2half2_rn(v1.x, v1.y);
    __half2 h3 = __floats2half2_rn(v1.z, v1.w);
    uint4 pack;
    pack.x = *(uint32_t*)&h0; pack.y = *(uint32_t*)&h1;
    pack.z = *(uint32_t*)&h2; pack.w = *(uint32_t*)&h3;
    *(uint4*)((__half*)g_Xh + base) = pack;
}

// ---------------------------------------------------------------------------
// Kernel 3: fp16 mma.sync m16n8k16 GEMM. 128x256 CTA, 256 threads, 5-stage
// cp.async pipeline. Y[m][n] = sum_k X[m][k]*W[n][k] + bias[n]
// ---------------------------------------------------------------------------
__global__ __launch_bounds__(256, 1)
void gemm_mma(const float* __restrict__ bias,
              float* __restrict__ Y) {
    extern __shared__ char smem[];
    const uint32_t sb = smem_u32(smem);
    const int tid = threadIdx.x, lane = tid & 31, wid = tid >> 5;
    const int wm = wid & 1, wn = wid >> 1;       // 2x4 warp grid, 64x64 warp tile
    const int bm = blockIdx.y * BM, bn = blockIdx.x * BN;

    const int mat = lane >> 3, rowin = lane & 7;
    // A x4 order: {m0-7 k0-7},{m8-15 k0-7},{m0-7 k8-15},{m8-15 k8-15} -> a0..a3
    const uint32_t a_base = (uint32_t)(wm * 64 + (mat & 1) * 8 + rowin) * ROWB + (mat >> 1) * 16;
    // B x4 order: {n0-7 k0-7},{n0-7 k8-15},{n8-15 k0-7},{n8-15 k8-15}
    const uint32_t b_base = (uint32_t)(wn * 64 + (mat >> 1) * 8 + rowin) * ROWB + (mat & 1) * 16;

    const __half* Xb = (const __half*)g_Xh + (size_t)bm * IN_DIM;
    const __half* Wb = (const __half*)g_Wh + (size_t)bn * IN_DIM;

    float acc[4][8][4];
#pragma unroll
    for (int i = 0; i < 4; i++)
#pragma unroll
        for (int j = 0; j < 8; j++)
#pragma unroll
            for (int k = 0; k < 4; k++) acc[i][j][k] = 0.f;

    // ---- async stage loader: 16B chunks (8 halves). A=512 chunks, B=1024. ----
    auto load_stage = [&](int s, int kt) {
        const uint32_t abase = sb + s * STAGE_BYTES;
        const uint32_t bbase = abase + A_SM_BYTES;
        const int kc = kt * BK;
#pragma unroll
        for (int i = 0; i < 2; i++) {
            int id = tid + i * 256;
            int r = id >> 2, c = (id & 3) * 8;               // 4 chunks per row
            CP_ASYNC16(abase + (uint32_t)r * ROWB + c * 2,
                       Xb + (size_t)r * IN_DIM + kc + c);
        }
#pragma unroll
        for (int i = 0; i < 4; i++) {
            int id = tid + i * 256;
            int r = id >> 2, c = (id & 3) * 8;
            CP_ASYNC16(bbase + (uint32_t)r * ROWB + c * 2,
                       Wb + (size_t)r * IN_DIM + kc + c);
        }
    };

    // ---- pipeline ----
#pragma unroll
    for (int s = 0; s < STAGES - 1; s++) { load_stage(s, s); CP_COMMIT(); }

    for (int kt = 0; kt < KT; kt++) {
        CP_WAIT(3);
        __syncthreads();
        if (kt + STAGES - 1 < KT) load_stage((kt + STAGES - 1) % STAGES, kt + STAGES - 1);
        CP_COMMIT();

        const int s = kt % STAGES;
        const uint32_t s_abase = sb + s * STAGE_BYTES + a_base;
        const uint32_t s_bbase = sb + s * STAGE_BYTES + A_SM_BYTES + b_base;

#pragma unroll
        for (int ks = 0; ks < BK / 16; ks++) {               // 2 k16-steps per kt
            uint32_t af[4][4], bf[4][4];
#pragma unroll
            for (int mt = 0; mt < 4; mt++)
                LDSM4(af[mt][0], af[mt][1], af[mt][2], af[mt][3],
                      s_abase + (uint32_t)mt * 16 * ROWB + ks * 32);
#pragma unroll
            for (int ng = 0; ng < 4; ng++)
                LDSM4(bf[ng][0], bf[ng][1], bf[ng][2], bf[ng][3],
                      s_bbase + (uint32_t)ng * 16 * ROWB + ks * 32);
#pragma unroll
            for (int mt = 0; mt < 4; mt++)
#pragma unroll
                for (int nt = 0; nt < 8; nt++)
                    mma_f16(acc[mt][nt], af[mt],
                            bf[nt >> 1][(nt & 1) * 2],
                            bf[nt >> 1][(nt & 1) * 2 + 1]);
        }
    }

    // ---- epilogue: c0/c1 at (row=group, col), c2/c3 at row+8 ----
    const int group = lane >> 2, tidg = lane & 3;
#pragma unroll
    for (int nt = 0; nt < 8; nt++) {
        int col = bn + wn * 64 + nt * 8 + tidg * 2;
        float b0 = bias[col], b1 = bias[col + 1];
#pragma unroll
        for (int mt = 0; mt < 4; mt++) {
            int r0 = bm + wm * 64 + mt * 16 + group;
            float2 v0, v1;
            v0.x = acc[mt][nt][0] + b0; v0.y = acc[mt][nt][1] + b1;
            v1.x = acc[mt][nt][2] + b0; v1.y = acc[mt][nt][3] + b1;
            *(float2*)(Y + (size_t)r0 * OUT_DIM + col)       = v0;
            *(float2*)(Y + (size_t)(r0 + 8) * OUT_DIM + col) = v1;
        }
    }
}

// ---------------------------------------------------------------------------
extern "C" void kernel_launch(void* const* d_in, const int* in_sizes, int n_in,
                              void* d_out, int out_size) {
    const float* x       = (const float*)d_in[0];
    const int*   indices = (const int*)  d_in[1];
    const float* lut     = (const float*)d_in[2];
    const float* A       = (const float*)d_in[3];
    const float* Bm      = (const float*)d_in[4];
    const float* mag     = (const float*)d_in[5];
    const float* bias    = (const float*)d_in[6];
    float* y = (float*)d_out;
    const int M = out_size / OUT_DIM;   // 8192

    stats_kernel<<<1, 128>>>(A, Bm, mag);
    build_w_kernel<<<(OUT_DIM * IN_DIM / 4) / 256, 256>>>(A, Bm, indices, lut);

    int total8 = M * IN_DIM / 8;
    convert_x_kernel<<<(total8 + 255) / 256, 256>>>(x, total8);

    static int configured = 0;
    if (!configured) {
        cudaFuncSetAttribute(gemm_mma, cudaFuncAttributeMaxDynamicSharedMemorySize, SMEM_TOTAL);
        configured = 1;
    }
    gemm_mma<<<dim3(OUT_DIM / BN, M / BM), 256, SMEM_TOTAL>>>(bias, y);
}

// round 9
// speedup vs baseline: 2.9775x; 1.2644x over previous
#include <cuda_runtime.h>
#include <cuda_fp16.h>
#include <math.h>
#include <stdint.h>

#define OUT_DIM 2048
#define IN_DIM  2048
#define MAXM    8192
#define RANK    4
#define NORM_EPS 1e-6f
#define MAG_EPS  1e-6f

// GEMM tiling: 128x128 CTA tile, 8 warps (64x32 warp tiles), fp16 operands,
// 2 CTAs/SM for 4 warps/SMSP.
#define BM 128
#define BN 128
#define BK 32
#define KT (IN_DIM / BK)          // 64 k-tiles
#define ROWB 80                   // bytes per smem row (40 halves): conflict-free LDSM
#define STAGES 4
#define A_SM_BYTES (BM * ROWB)               // 10240
#define STAGE_BYTES ((BM + BN) * ROWB)       // 20480
#define SMEM_TOTAL (STAGES * STAGE_BYTES)    // 81920

// scratch
__device__ __half g_Wh[OUT_DIM * IN_DIM];    // fp16 effective weight [out][in]
__device__ __half g_Xh[MAXM * IN_DIM];       // fp16 copy of X
__device__ float  g_stats[3 * RANK];         // [0..3]=normA, [4..7]=normB, [8..11]=g

// ---------------------------------------------------------------------------
// PTX helpers (sm_80+ portable)
// ---------------------------------------------------------------------------
__device__ __forceinline__ uint32_t smem_u32(const void* p) {
    uint32_t a;
    asm("{ .reg .u64 t; cvta.to.shared.u64 t, %1; cvt.u32.u64 %0, t; }" : "=r"(a) : "l"(p));
    return a;
}
#define CP_ASYNC16(dst, src) \
    asm volatile("cp.async.cg.shared.global [%0], [%1], 16;" :: "r"(dst), "l"(src))
#define CP_COMMIT() asm volatile("cp.async.commit_group;" ::: "memory")
#define CP_WAIT(n)  asm volatile("cp.async.wait_group %0;" :: "n"(n) : "memory")
#define LDSM4(r0, r1, r2, r3, addr) \
    asm volatile("ldmatrix.sync.aligned.m8n8.x4.shared.b16 {%0,%1,%2,%3}, [%4];" \
        : "=r"(r0), "=r"(r1), "=r"(r2), "=r"(r3) : "r"(addr))

__device__ __forceinline__ void mma_f16(float* d, const uint32_t* a, uint32_t b0, uint32_t b1) {
    asm volatile("mma.sync.aligned.m16n8k16.row.col.f32.f16.f16.f32 "
        "{%0,%1,%2,%3}, {%4,%5,%6,%7}, {%8,%9}, {%0,%1,%2,%3};"
        : "+f"(d[0]), "+f"(d[1]), "+f"(d[2]), "+f"(d[3])
        : "r"(a[0]), "r"(a[1]), "r"(a[2]), "r"(a[3]), "r"(b0), "r"(b1));
}

// ---------------------------------------------------------------------------
// Kernel 1: per-rank norms + softplus magnitude
// ---------------------------------------------------------------------------
__global__ void stats_kernel(const float* __restrict__ A,
                             const float* __restrict__ Bm,
                             const float* __restrict__ mag) {
    int r = threadIdx.x >> 5, lane = threadIdx.x & 31;
    float sa = 0.f, sb = 0.f;
    for (int o = lane; o < OUT_DIM; o += 32) { float v = A[o * RANK + r]; sa += v * v; }
    for (int i = lane; i < IN_DIM; i += 32)  { float v = Bm[r * IN_DIM + i]; sb += v * v; }
#pragma unroll
    for (int off = 16; off; off >>= 1) {
        sa += __shfl_xor_sync(0xffffffffu, sa, off);
        sb += __shfl_xor_sync(0xffffffffu, sb, off);
    }
    if (lane == 0) {
        g_stats[r]        = fmaxf(sqrtf(sa), NORM_EPS);
        g_stats[RANK + r] = fmaxf(sqrtf(sb), NORM_EPS);
        float m = mag[r];
        float sp = (m > 15.f) ? m : log1pf(expf(m));
        g_stats[2 * RANK + r] = sp + MAG_EPS;
    }
}

// ---------------------------------------------------------------------------
// Kernel 2: materialize W[o][i] = lut[idx]*sum_r coef[o][r]*|B[r][i]| as fp16
// ---------------------------------------------------------------------------
__global__ void build_w_kernel(const float* __restrict__ A,
                               const float* __restrict__ Bm,
                               const int*   __restrict__ idx,
                               const float* __restrict__ lut) {
    int t = blockIdx.x * blockDim.x + threadIdx.x;
    int per_row = IN_DIM / 4;
    int o  = t / per_row;
    int i4 = (t - o * per_row) * 4;

    float coef[RANK];
#pragma unroll
    for (int r = 0; r < RANK; r++)
        coef[r] = fabsf(A[o * RANK + r]) * g_stats[2 * RANK + r]
                  / (g_stats[r] * g_stats[RANK + r]);

    float s[4] = {0.f, 0.f, 0.f, 0.f};
#pragma unroll
    for (int r = 0; r < RANK; r++) {
        float4 bv = *(const float4*)(Bm + r * IN_DIM + i4);
        s[0] += coef[r] * fabsf(bv.x);
        s[1] += coef[r] * fabsf(bv.y);
        s[2] += coef[r] * fabsf(bv.z);
        s[3] += coef[r] * fabsf(bv.w);
    }
    int4 iv = *(const int4*)(idx + o * IN_DIM + i4);
    __half2 h0 = __floats2half2_rn(lut[iv.x] * s[0], lut[iv.y] * s[1]);
    __half2 h1 = __floats2half2_rn(lut[iv.z] * s[2], lut[iv.w] * s[3]);
    uint2 pack;
    pack.x = *(uint32_t*)&h0;
    pack.y = *(uint32_t*)&h1;
    *(uint2*)((__half*)g_Wh + (size_t)o * IN_DIM + i4) = pack;
}

// ---------------------------------------------------------------------------
// Kernel 2b: X fp32 -> fp16 (8 elems/thread)
// ---------------------------------------------------------------------------
__global__ void convert_x_kernel(const float* __restrict__ X, int total8) {
    int t = blockIdx.x * blockDim.x + threadIdx.x;
    if (t >= total8) return;
    size_t base = (size_t)t * 8;
    float4 v0 = *(const float4*)(X + base);
    float4 v1 = *(const float4*)(X + base + 4);
    __half2 h0 = __floats2half2_rn(v0.x, v0.y);
    __half2 h1 = __floats2half2_rn(v0.z, v0.w);
    __half2 h2 = __floats2half2_rn(v1.x, v1.y);
    __half2 h3 = __floats2half2_rn(v1.z, v1.w);
    uint4 pack;
    pack.x = *(uint32_t*)&h0; pack.y = *(uint32_t*)&h1;
    pack.z = *(uint32_t*)&h2; pack.w = *(uint32_t*)&h3;
    *(uint4*)((__half*)g_Xh + base) = pack;
}

// ---------------------------------------------------------------------------
// Kernel 3: fp16 mma.sync m16n8k16 GEMM. 128x128 CTA, 256 threads (8 warps,
// 64x32 warp tiles), 4-stage cp.async pipeline, 2 CTAs/SM.
// Y[m][n] = sum_k X[m][k]*W[n][k] + bias[n]
// ---------------------------------------------------------------------------
__global__ __launch_bounds__(256, 2)
void gemm_mma(const float* __restrict__ bias,
              float* __restrict__ Y) {
    extern __shared__ char smem[];
    const uint32_t sb = smem_u32(smem);
    const int tid = threadIdx.x, lane = tid & 31, wid = tid >> 5;
    const int wm = wid & 1, wn = wid >> 1;       // 2x4 warp grid, 64x32 warp tile
    const int bm = blockIdx.y * BM, bn = blockIdx.x * BN;

    const int mat = lane >> 3, rowin = lane & 7;
    // A x4 order: {m0-7 k0-7},{m8-15 k0-7},{m0-7 k8-15},{m8-15 k8-15}
    const uint32_t a_base = (uint32_t)(wm * 64 + (mat & 1) * 8 + rowin) * ROWB + (mat >> 1) * 16;
    // B x4 order: {n0-7 k0-7},{n0-7 k8-15},{n8-15 k0-7},{n8-15 k8-15}
    const uint32_t b_base = (uint32_t)(wn * 32 + (mat >> 1) * 8 + rowin) * ROWB + (mat & 1) * 16;

    const __half* Xb = (const __half*)g_Xh + (size_t)bm * IN_DIM;
    const __half* Wb = (const __half*)g_Wh + (size_t)bn * IN_DIM;

    float acc[4][4][4];
#pragma unroll
    for (int i = 0; i < 4; i++)
#pragma unroll
        for (int j = 0; j < 4; j++)
#pragma unroll
            for (int k = 0; k < 4; k++) acc[i][j][k] = 0.f;

    // ---- async stage loader: 16B chunks (8 halves). A=512 chunks, B=512. ----
    auto load_stage = [&](int s, int kt) {
        const uint32_t abase = sb + s * STAGE_BYTES;
        const uint32_t bbase = abase + A_SM_BYTES;
        const int kc = kt * BK;
#pragma unroll
        for (int i = 0; i < 2; i++) {
            int id = tid + i * 256;
            int r = id >> 2, c = (id & 3) * 8;               // 4 chunks per row
            CP_ASYNC16(abase + (uint32_t)r * ROWB + c * 2,
                       Xb + (size_t)r * IN_DIM + kc + c);
        }
#pragma unroll
        for (int i = 0; i < 2; i++) {
            int id = tid + i * 256;
            int r = id >> 2, c = (id & 3) * 8;
            CP_ASYNC16(bbase + (uint32_t)r * ROWB + c * 2,
                       Wb + (size_t)r * IN_DIM + kc + c);
        }
    };

    // ---- pipeline ----
#pragma unroll
    for (int s = 0; s < STAGES - 1; s++) { load_stage(s, s); CP_COMMIT(); }

    for (int kt = 0; kt < KT; kt++) {
        CP_WAIT(2);
        __syncthreads();
        if (kt + STAGES - 1 < KT) load_stage((kt + STAGES - 1) & 3, kt + STAGES - 1);
        CP_COMMIT();

        const int s = kt & 3;
        const uint32_t s_abase = sb + s * STAGE_BYTES + a_base;
        const uint32_t s_bbase = sb + s * STAGE_BYTES + A_SM_BYTES + b_base;

#pragma unroll
        for (int ks = 0; ks < BK / 16; ks++) {               // 2 k16-steps per kt
            uint32_t af[4][4], bf[2][4];
#pragma unroll
            for (int mt = 0; mt < 4; mt++)
                LDSM4(af[mt][0], af[mt][1], af[mt][2], af[mt][3],
                      s_abase + (uint32_t)mt * 16 * ROWB + ks * 32);
#pragma unroll
            for (int ng = 0; ng < 2; ng++)
                LDSM4(bf[ng][0], bf[ng][1], bf[ng][2], bf[ng][3],
                      s_bbase + (uint32_t)ng * 16 * ROWB + ks * 32);
#pragma unroll
            for (int mt = 0; mt < 4; mt++)
#pragma unroll
                for (int nt = 0; nt < 4; nt++)
                    mma_f16(acc[mt][nt], af[mt],
                            bf[nt >> 1][(nt & 1) * 2],
                            bf[nt >> 1][(nt & 1) * 2 + 1]);
        }
    }

    // ---- epilogue: c0/c1 at (row=group, col), c2/c3 at row+8 ----
    const int group = lane >> 2, tidg = lane & 3;
#pragma unroll
    for (int nt = 0; nt < 4; nt++) {
        int col = bn + wn * 32 + nt * 8 + tidg * 2;
        float b0 = bias[col], b1 = bias[col + 1];
#pragma unroll
        for (int mt = 0; mt < 4; mt++) {
            int r0 = bm + wm * 64 + mt * 16 + group;
            float2 v0, v1;
            v0.x = acc[mt][nt][0] + b0; v0.y = acc[mt][nt][1] + b1;
            v1.x = acc[mt][nt][2] + b0; v1.y = acc[mt][nt][3] + b1;
            *(float2*)(Y + (size_t)r0 * OUT_DIM + col)       = v0;
            *(float2*)(Y + (size_t)(r0 + 8) * OUT_DIM + col) = v1;
        }
    }
}

// ---------------------------------------------------------------------------
extern "C" void kernel_launch(void* const* d_in, const int* in_sizes, int n_in,
                              void* d_out, int out_size) {
    const float* x       = (const float*)d_in[0];
    const int*   indices = (const int*)  d_in[1];
    const float* lut     = (const float*)d_in[2];
    const float* A       = (const float*)d_in[3];
    const float* Bm      = (const float*)d_in[4];
    const float* mag     = (const float*)d_in[5];
    const float* bias    = (const float*)d_in[6];
    float* y = (float*)d_out;
    const int M = out_size / OUT_DIM;   // 8192

    stats_kernel<<<1, 128>>>(A, Bm, mag);
    build_w_kernel<<<(OUT_DIM * IN_DIM / 4) / 256, 256>>>(A, Bm, indices, lut);

    int total8 = M * IN_DIM / 8;
    convert_x_kernel<<<(total8 + 255) / 256, 256>>>(x, total8);

    static int configured = 0;
    if (!configured) {
        cudaFuncSetAttribute(gemm_mma, cudaFuncAttributeMaxDynamicSharedMemorySize, SMEM_TOTAL);
        configured = 1;
    }
    gemm_mma<<<dim3(OUT_DIM / BN, M / BM), 256, SMEM_TOTAL>>>(bias, y);
}